// round 5
// baseline (speedup 1.0000x reference)
#include <cuda_runtime.h>
#include <math.h>

#define D      690
#define D2     345      // D/2 (float2 per row)
#define R      53
#define NBAGS  25000
#define NTOT   200000
#define CH     32       // rows per chunk in K1

// Scratch for bag attention vectors (allowed: __device__ global array)
__device__ __align__(16) float g_att[(size_t)NBAGS * D];

// ---------------------------------------------------------------------------
// Kernel 1: one warp per bag, chunked two-phase softmax-attention.
// Phase 1: independent per-row dots, per-lane partials -> smem transpose
//          reduction (no per-row shuffle chains).
// Phase 2: re-read chunk rows (L1-hot) for the weighted accumulation.
// ---------------------------------------------------------------------------
__global__ __launch_bounds__(256) void bag_att_kernel(
    const float* __restrict__ repre,
    const float* __restrict__ rel,
    const int* __restrict__ scope,     // int32
    const int* __restrict__ labels)    // int32
{
    __shared__ float sm[8][CH][33];    // 33.8 KB: per-warp partial matrix

    const int wl   = threadIdx.x >> 5;             // warp in block
    const int w    = blockIdx.x * 8 + wl;          // bag id
    if (w >= NBAGS) return;
    const int lane = threadIdx.x & 31;

    const int s = scope[2 * w];
    const int e = scope[2 * w + 1];
    const int n = e - s;

    const float2* rp = (const float2*)repre;
    const float2* rl = (const float2*)rel;
    float (*pm)[33] = sm[wl];

    float2 acc[11];
    #pragma unroll
    for (int j = 0; j < 11; ++j) acc[j] = make_float2(0.f, 0.f);
    const bool tail = (lane < (D2 - 320));         // 25 lanes own k=lane+320

    float run_m = -INFINITY;
    float run_s = 0.f;

    for (int c0 = 0; c0 < n; c0 += CH) {
        const int cn = min(CH, n - c0);

        // ---- phase 1: per-row per-lane partial dots (rows independent) ----
        for (int i = 0; i < cn; ++i) {
            const int row = s + c0 + i;
            const int lab = labels[row];           // uniform -> broadcast
            const float2* a = rp + (size_t)row * D2;
            const float2* v = rl + (size_t)lab * D2;
            float p0 = 0.f, p1 = 0.f, p2 = 0.f, p3 = 0.f;
            #pragma unroll
            for (int j = 0; j < 10; j += 2) {
                const int ka = lane + 32 * j;
                const int kb = lane + 32 * (j + 1);
                float2 a0 = a[ka], v0 = v[ka];
                float2 a1 = a[kb], v1 = v[kb];
                p0 = fmaf(a0.x, v0.x, p0);
                p1 = fmaf(a0.y, v0.y, p1);
                p2 = fmaf(a1.x, v1.x, p2);
                p3 = fmaf(a1.y, v1.y, p3);
            }
            if (tail) {
                const int k = lane + 320;
                float2 a0 = a[k], v0 = v[k];
                p0 = fmaf(a0.x, v0.x, p0);
                p1 = fmaf(a0.y, v0.y, p1);
            }
            pm[i][lane] = (p0 + p1) + (p2 + p3);
        }
        __syncwarp();

        // ---- transpose reduction: lane j sums row j's 32 partials ----
        float l = -INFINITY;
        if (lane < cn) {
            float s0 = 0.f, s1 = 0.f, s2 = 0.f, s3 = 0.f;
            #pragma unroll
            for (int k = 0; k < 32; k += 4) {
                s0 += pm[lane][k];
                s1 += pm[lane][k + 1];
                s2 += pm[lane][k + 2];
                s3 += pm[lane][k + 3];
            }
            l = (s0 + s1) + (s2 + s3);
        }

        // ---- chunk softmax bookkeeping (once per chunk) ----
        float cm = l;
        #pragma unroll
        for (int o = 16; o; o >>= 1)
            cm = fmaxf(cm, __shfl_xor_sync(0xffffffffu, cm, o));
        const float m_new = fmaxf(run_m, cm);
        const float sc    = __expf(run_m - m_new);      // 0 on first chunk
        const float p     = (lane < cn) ? __expf(l - m_new) : 0.f;
        float cs = p;
        #pragma unroll
        for (int o = 16; o; o >>= 1)
            cs += __shfl_xor_sync(0xffffffffu, cs, o);
        run_s = run_s * sc + cs;
        run_m = m_new;
        #pragma unroll
        for (int j = 0; j < 11; ++j) { acc[j].x *= sc; acc[j].y *= sc; }

        // ---- phase 2: weighted accumulation (rows L1-hot from phase 1) ----
        for (int i = 0; i < cn; ++i) {
            const float pi = __shfl_sync(0xffffffffu, p, i);
            const float2* a = rp + (size_t)(s + c0 + i) * D2;
            #pragma unroll
            for (int j = 0; j < 10; ++j) {
                const float2 av = a[lane + 32 * j];
                acc[j].x = fmaf(pi, av.x, acc[j].x);
                acc[j].y = fmaf(pi, av.y, acc[j].y);
            }
            if (tail) {
                const float2 av = a[lane + 320];
                acc[10].x = fmaf(pi, av.x, acc[10].x);
                acc[10].y = fmaf(pi, av.y, acc[10].y);
            }
        }
        __syncwarp();   // pm reused next chunk
    }

    const float inv = 1.f / run_s;
    float2* outp = (float2*)(g_att + (size_t)w * D);
    #pragma unroll
    for (int j = 0; j < 10; ++j) {
        float2 o = acc[j];
        o.x *= inv; o.y *= inv;
        outp[lane + 32 * j] = o;
    }
    if (tail) {
        float2 o = acc[10];
        o.x *= inv; o.y *= inv;
        outp[lane + 320] = o;
    }
}

// ---------------------------------------------------------------------------
// Kernel 2: logits = g_att (25000x690) @ rel^T (690x53) + bias
// Block tile 64m x 64r(pad), thread tile 4m x 4r, Kc = 32. B stored
// pre-splatted ((f,f) packed) so inner loop = 3x LDS.128 + 8x FFMA2 per k.
// ---------------------------------------------------------------------------
#define GM  64
#define GKC 32

#define FMA2(d, a, b) \
    asm("fma.rn.f32x2 %0, %1, %2, %0;" : "+l"(d) : "l"(a), "l"(b))

__global__ __launch_bounds__(256) void logits_gemm_kernel(
    const float* __restrict__ rel,
    const float* __restrict__ bias,
    float* __restrict__ out)
{
    __shared__ __align__(16) float a_s[GKC][GM];                  //  8 KB [k][m]
    __shared__ __align__(16) unsigned long long b_s2[GKC][64];    // 16 KB [k][r] splatted

    const int tid = threadIdx.x;
    const int tx  = tid & 15;    // r group: r = tx*4 + j
    const int ty  = tid >> 4;    // m group: m = m0 + ty*4 + i
    const int m0  = blockIdx.x * GM;

    // loader mapping: 64 rows x 8 consecutive k per thread
    const int lrow = tid & 63;          // m (A) or r (B) within tile
    const int kq   = (tid >> 6) * 8;    // k offset: 0,8,16,24
    const int gm   = m0 + lrow;
    const bool mok = (gm < NBAGS);
    const float* asrc = g_att + (size_t)gm * D;
    const float* bsrc = rel + (size_t)lrow * D;
    const bool rok = (lrow < R);

    unsigned long long acc2[2][4];      // [m-pair][r]
    #pragma unroll
    for (int i = 0; i < 2; ++i)
        #pragma unroll
        for (int j = 0; j < 4; ++j) acc2[i][j] = 0ull;

    for (int kc = 0; kc < D; kc += GKC) {
        #pragma unroll
        for (int t = 0; t < 4; ++t) {
            const int k = kc + kq + 2 * t;
            // A tile
            float2 va = make_float2(0.f, 0.f);
            if (mok && k < D) va = *(const float2*)(asrc + k);
            a_s[kq + 2 * t][lrow]     = va.x;
            a_s[kq + 2 * t + 1][lrow] = va.y;
            // B tile (splatted)
            float2 vb = make_float2(0.f, 0.f);
            if (rok && k < D) vb = *(const float2*)(bsrc + k);
            unsigned long long sx, sy;
            asm("mov.b64 %0, {%1, %1};" : "=l"(sx) : "r"(__float_as_uint(vb.x)));
            asm("mov.b64 %0, {%1, %1};" : "=l"(sy) : "r"(__float_as_uint(vb.y)));
            b_s2[kq + 2 * t][lrow]     = sx;
            b_s2[kq + 2 * t + 1][lrow] = sy;
        }
        __syncthreads();

        #pragma unroll
        for (int k = 0; k < GKC; ++k) {
            const ulonglong2 ap  = *(const ulonglong2*)&a_s[k][ty * 4];
            const ulonglong2 b01 = *(const ulonglong2*)&b_s2[k][tx * 4];
            const ulonglong2 b23 = *(const ulonglong2*)&b_s2[k][tx * 4 + 2];
            FMA2(acc2[0][0], ap.x, b01.x);
            FMA2(acc2[0][1], ap.x, b01.y);
            FMA2(acc2[0][2], ap.x, b23.x);
            FMA2(acc2[0][3], ap.x, b23.y);
            FMA2(acc2[1][0], ap.y, b01.x);
            FMA2(acc2[1][1], ap.y, b01.y);
            FMA2(acc2[1][2], ap.y, b23.x);
            FMA2(acc2[1][3], ap.y, b23.y);
        }
        __syncthreads();
    }

    // ---- epilogue ----
    #pragma unroll
    for (int j = 0; j < 4; ++j) {
        const int r = tx * 4 + j;
        if (r >= R) continue;
        const float bi = bias[r];
        #pragma unroll
        for (int i = 0; i < 2; ++i) {
            unsigned int lo, hi;
            asm("mov.b64 {%0, %1}, %2;" : "=r"(lo), "=r"(hi) : "l"(acc2[i][j]));
            const int m = m0 + ty * 4 + 2 * i;
            if (m < NBAGS)     out[(size_t)m * R + r]       = __uint_as_float(lo) + bi;
            if (m + 1 < NBAGS) out[(size_t)(m + 1) * R + r] = __uint_as_float(hi) + bi;
        }
    }
}

// ---------------------------------------------------------------------------
extern "C" void kernel_launch(void* const* d_in, const int* in_sizes, int n_in,
                              void* d_out, int out_size)
{
    const float* repre  = (const float*)d_in[0];   // (N, D) f32
    const float* rel    = (const float*)d_in[1];   // (R, D) f32
    const float* bias   = (const float*)d_in[2];   // (R,)   f32
    const int*   scope  = (const int*)d_in[3];     // (NBAGS, 2) i32
    const int*   labels = (const int*)d_in[4];     // (N,)   i32
    float* out = (float*)d_out;                    // (NBAGS, R) f32

    const int blocks1 = (NBAGS + 7) / 8;           // 8 warps (bags) per block
    bag_att_kernel<<<blocks1, 256>>>(repre, rel, scope, labels);

    const int blocks2 = (NBAGS + GM - 1) / GM;     // 391
    logits_gemm_kernel<<<blocks2, 256>>>(rel, bias, out);
}

// round 8
// speedup vs baseline: 1.8657x; 1.8657x over previous
#include <cuda_runtime.h>
#include <math.h>

#define D      690
#define D2     345      // D/2 (float2 per row)
#define R      53
#define NBAGS  25000
#define NTOT   200000

// __device__ scratch (allowed)
__device__ __align__(16) float g_att[(size_t)NBAGS * D];   // 69 MB
__device__ float g_logit[NTOT];
__device__ float g_w[NTOT];

// ---------------------------------------------------------------------------
// Kernel A: one warp per row: g_logit[i] = dot(repre[i], rel[labels[i]])
// Fully independent warps -> latency trivially hidden -> DRAM-bound.
// ---------------------------------------------------------------------------
__global__ __launch_bounds__(256) void logit_kernel(
    const float* __restrict__ repre,
    const float* __restrict__ rel,
    const int* __restrict__ labels)
{
    const int w = (blockIdx.x * 256 + threadIdx.x) >> 5;
    if (w >= NTOT) return;
    const int lane = threadIdx.x & 31;

    const float2* a = (const float2*)repre + (size_t)w * D2;
    const float2* v = (const float2*)rel + (size_t)labels[w] * D2;

    float p0 = 0.f, p1 = 0.f, p2 = 0.f, p3 = 0.f;
    #pragma unroll
    for (int j = 0; j < 10; j += 2) {
        const int ka = lane + 32 * j;
        const int kb = ka + 32;
        float2 a0 = a[ka], v0 = v[ka];
        float2 a1 = a[kb], v1 = v[kb];
        p0 = fmaf(a0.x, v0.x, p0);
        p1 = fmaf(a0.y, v0.y, p1);
        p2 = fmaf(a1.x, v1.x, p2);
        p3 = fmaf(a1.y, v1.y, p3);
    }
    if (lane < 25) {   // tail: k = lane + 320 < 345
        const int k = lane + 320;
        float2 a0 = a[k], v0 = v[k];
        p0 = fmaf(a0.x, v0.x, p0);
        p1 = fmaf(a0.y, v0.y, p1);
    }
    float part = (p0 + p1) + (p2 + p3);
    #pragma unroll
    for (int o = 16; o; o >>= 1)
        part += __shfl_xor_sync(0xffffffffu, part, o);
    if (lane == 0) g_logit[w] = part;
}

// ---------------------------------------------------------------------------
// Kernel B: one warp per bag: softmax over g_logit segment -> normalized g_w.
// ---------------------------------------------------------------------------
__global__ __launch_bounds__(256) void weight_kernel(const int* __restrict__ scope)
{
    const int b = (blockIdx.x * 256 + threadIdx.x) >> 5;
    if (b >= NBAGS) return;
    const int lane = threadIdx.x & 31;
    const int s = scope[2 * b];
    const int e = scope[2 * b + 1];

    float m = -INFINITY;
    for (int i = s + lane; i < e; i += 32) m = fmaxf(m, g_logit[i]);
    #pragma unroll
    for (int o = 16; o; o >>= 1)
        m = fmaxf(m, __shfl_xor_sync(0xffffffffu, m, o));

    float sum = 0.f;
    for (int i = s + lane; i < e; i += 32) {
        const float ev = __expf(g_logit[i] - m);
        g_w[i] = ev;
        sum += ev;
    }
    #pragma unroll
    for (int o = 16; o; o >>= 1)
        sum += __shfl_xor_sync(0xffffffffu, sum, o);

    const float inv = 1.f / sum;
    for (int i = s + lane; i < e; i += 32) g_w[i] *= inv;
}

// ---------------------------------------------------------------------------
// Kernel C: one warp per bag: g_att[b] = sum_i g_w[i] * repre[i].
// No shuffles, no exp -> pure stream with deep MLP.
// ---------------------------------------------------------------------------
__global__ __launch_bounds__(256) void wsum_kernel(
    const float* __restrict__ repre,
    const int* __restrict__ scope)
{
    const int b = (blockIdx.x * 256 + threadIdx.x) >> 5;
    if (b >= NBAGS) return;
    const int lane = threadIdx.x & 31;
    const int s = scope[2 * b];
    const int e = scope[2 * b + 1];
    const bool tail = (lane < 25);

    float2 acc[11];
    #pragma unroll
    for (int j = 0; j < 11; ++j) acc[j] = make_float2(0.f, 0.f);

    const float2* rp = (const float2*)repre;
    for (int row = s; row < e; ++row) {
        const float pi = g_w[row];                 // broadcast load
        const float2* a = rp + (size_t)row * D2;
        #pragma unroll
        for (int j = 0; j < 10; ++j) {
            const float2 av = a[lane + 32 * j];
            acc[j].x = fmaf(pi, av.x, acc[j].x);
            acc[j].y = fmaf(pi, av.y, acc[j].y);
        }
        if (tail) {
            const float2 av = a[lane + 320];
            acc[10].x = fmaf(pi, av.x, acc[10].x);
            acc[10].y = fmaf(pi, av.y, acc[10].y);
        }
    }

    float2* outp = (float2*)(g_att + (size_t)b * D);
    #pragma unroll
    for (int j = 0; j < 10; ++j) outp[lane + 32 * j] = acc[j];
    if (tail) outp[lane + 320] = acc[10];
}

// ---------------------------------------------------------------------------
// Kernel D: out = g_att (25000x690) @ rel^T (690x53) + bias.
// Lane owns one m row (64 rows / 2-warp block). Conflict-free smem:
//   a_s[k][tid]   : 4B stride-1 per lane (N=1)
//   b_s pairs     : broadcast ulonglong2 reads (N=1)
// Inner loop per k: 1 LDS.32 + 1 splat + 14 LDS.128(bcast) + 28 FFMA2.
// ---------------------------------------------------------------------------
#define BM  64
#define KC  16

#define FMA2(d, a, b) \
    asm("fma.rn.f32x2 %0, %1, %2, %0;" : "+l"(d) : "l"(a), "l"(b))

__global__ __launch_bounds__(64) void gemm_kernel(
    const float* __restrict__ rel,
    const float* __restrict__ bias,
    float* __restrict__ out)
{
    __shared__ __align__(16) float a_s[KC][BM];   // 4 KB [k][m]
    __shared__ __align__(16) float b_s[KC][68];   // 4.25 KB [k][r], pad 68

    const int tid = threadIdx.x;
    const int m0  = blockIdx.x * BM;
    const int gm  = m0 + tid;
    const bool mok = (gm < NBAGS);
    const float* asrc = g_att + (size_t)gm * D;

    unsigned long long acc2[28];   // r pairs (0,1)..(54,55); r>=53 padded 0
    #pragma unroll
    for (int j = 0; j < 28; ++j) acc2[j] = 0ull;

    for (int kc = 0; kc < D; kc += KC) {
        // ---- A tile: thread loads 16 consecutive k of its own row ----
        #pragma unroll
        for (int t = 0; t < 8; ++t) {
            const int k = kc + 2 * t;
            float2 v = make_float2(0.f, 0.f);
            if (mok && k < D) v = *(const float2*)(asrc + k);   // D even -> safe
            a_s[2 * t][tid]     = v.x;
            a_s[2 * t + 1][tid] = v.y;
        }
        // ---- B tile: coalesced (k fastest across lanes), zero-padded ----
        #pragma unroll
        for (int t = 0; t < 16; ++t) {
            const int idx = tid + 64 * t;        // 0..1023
            const int k = idx & 15;
            const int r = idx >> 4;              // 0..63
            float v = 0.f;
            if (r < R && kc + k < D) v = rel[(size_t)r * D + kc + k];
            b_s[k][r] = v;
        }
        __syncthreads();

        #pragma unroll
        for (int k = 0; k < KC; ++k) {
            const float av = a_s[k][tid];
            unsigned long long av2;
            asm("mov.b64 %0, {%1, %1};" : "=l"(av2) : "r"(__float_as_uint(av)));
            #pragma unroll
            for (int j = 0; j < 14; ++j) {
                const ulonglong2 b2 = *(const ulonglong2*)&b_s[k][4 * j];  // bcast
                FMA2(acc2[2 * j],     av2, b2.x);
                FMA2(acc2[2 * j + 1], av2, b2.y);
            }
        }
        __syncthreads();
    }

    if (mok) {
        #pragma unroll
        for (int j = 0; j < 27; ++j) {           // r pairs up to (52,53)
            unsigned int lo, hi;
            asm("mov.b64 {%0, %1}, %2;" : "=r"(lo), "=r"(hi) : "l"(acc2[j]));
            const int r = 2 * j;
            out[(size_t)gm * R + r] = __uint_as_float(lo) + bias[r];
            if (r + 1 < R)
                out[(size_t)gm * R + r + 1] = __uint_as_float(hi) + bias[r + 1];
        }
    }
}

// ---------------------------------------------------------------------------
extern "C" void kernel_launch(void* const* d_in, const int* in_sizes, int n_in,
                              void* d_out, int out_size)
{
    const float* repre  = (const float*)d_in[0];   // (N, D) f32
    const float* rel    = (const float*)d_in[1];   // (R, D) f32
    const float* bias   = (const float*)d_in[2];   // (R,)   f32
    const int*   scope  = (const int*)d_in[3];     // (NBAGS, 2) i32
    const int*   labels = (const int*)d_in[4];     // (N,)   i32
    float* out = (float*)d_out;                    // (NBAGS, R) f32

    logit_kernel<<<(NTOT + 7) / 8, 256>>>(repre, rel, labels);     // 25000 blocks
    weight_kernel<<<(NBAGS + 7) / 8, 256>>>(scope);                // 3125 blocks
    wsum_kernel<<<(NBAGS + 7) / 8, 256>>>(repre, scope);           // 3125 blocks
    gemm_kernel<<<(NBAGS + BM - 1) / BM, BM>>>(rel, bias, out);    // 391 blocks
}